// round 13
// baseline (speedup 1.0000x reference)
#include <cuda_runtime.h>
#include <cuda_fp16.h>
#include <cstdint>

#define Hh 64
#define Ww 64
#define Cc 128
#define Dd 256
#define NCH 18                  // K chunks of 64, k = tap*128 + c (tap-major)
#define A_OFF 67584             // tile bytes: 4*66*128*2 = 67584 (1024-aligned)
#define SMEM_MAIN (67584 + 32768 + 1024)

__device__ __half g_xT[(size_t)32 * 64 * 64 * 128];   // [img][y][x][c]
// Pre-permuted fp16 weights: u32 [chunk][dblk][ks2(4)][warp_m(2)][mt(4)][lane(32)][slot(4)]
__device__ __half g_A[NCH * 2 * 8192];

static __device__ __forceinline__ uint32_t smem_u32(const void* p) {
    uint32_t a;
    asm("{ .reg .u64 t; cvta.to.shared.u64 t, %1; cvt.u32.u64 %0, t; }" : "=r"(a) : "l"(p));
    return a;
}
static __device__ __forceinline__ void cp16(uint32_t saddr, const void* g) {
    asm volatile("cp.async.ca.shared.global [%0], [%1], 16;" :: "r"(saddr), "l"(g));
}

// ---------------------------------------------------------------------------
// Transpose x [img][c][y][x] f32 -> g_xT [img][y][x][c] fp16. Grid (64 y, 32 img).
// ---------------------------------------------------------------------------
__global__ void transp_kernel(const float* __restrict__ x) {
    __shared__ __half sm[64 * 132];
    const int tid = threadIdx.x;
    const int y = blockIdx.x, img = blockIdx.y;
    const float2* src = (const float2*)x;
    #pragma unroll
    for (int i = 0; i < 16; i++) {
        int e = tid + i * 256;             // 4096 float2
        int c = e >> 5, xp = e & 31;
        float2 v = src[(((size_t)img * 128 + c) * 4096 + y * 64) / 2 + xp];
        sm[(2 * xp) * 132 + c]     = __float2half_rn(v.x);
        sm[(2 * xp + 1) * 132 + c] = __float2half_rn(v.y);
    }
    __syncthreads();
    uint32_t* dst = (uint32_t*)g_xT + ((size_t)(img * 64 + y) * 64) * 64;
    #pragma unroll
    for (int i = 0; i < 16; i++) {
        int e = tid + i * 256;             // 4096 u32
        int xx = e >> 6, cp = e & 63;
        dst[xx * 64 + cp] = *(const uint32_t*)&sm[xx * 132 + 2 * cp];
    }
}

// ---------------------------------------------------------------------------
// Build A in m16n8k16 fragment order, K tap-major: k = tap*128 + c.
// ---------------------------------------------------------------------------
__global__ void build_A_kernel(const float* __restrict__ c0,
                               const float* __restrict__ c1,
                               const float* __restrict__ c2) {
    int d = blockIdx.x, t = threadIdx.x;
    __shared__ float sA[72];
    if (t < 72) {
        int r = t / 9, k = t % 9, kh = k / 3, kw = k % 3;
        float a = 0.f;
        #pragma unroll
        for (int s = 0; s < 4; s++)
            a += c1[d * 96 + r * 12 + kh * 4 + s] * c2[d * 12 + s * 3 + kw];
        sA[t] = a;
    }
    __syncthreads();
    int c = t;
    float cr[8];
    #pragma unroll
    for (int r = 0; r < 8; r++) cr[r] = c0[d * 1024 + c * 8 + r];

    const int dblk = d >> 7, ml = d & 127;
    const int mhalf = ml >> 6, mt = (ml >> 4) & 3, mm = ml & 15;
    const int g = mm & 7, hi = mm >> 3;

    #pragma unroll
    for (int tap = 0; tap < 9; tap++) {
        float w = 0.f;
        #pragma unroll
        for (int r = 0; r < 8; r++) w += cr[r] * sA[r * 9 + tap];
        int chunk = tap * 2 + (c >> 6);
        int kr = c & 63;
        int ks2 = kr >> 4, kk = kr & 15;
        int tig = (kk >> 1) & 3, par = kk & 1, khi = kk >> 3;
        int lane = g * 4 + tig, slot = khi * 2 + hi;
        size_t u32i = (size_t)(chunk * 2 + dblk) * 4096 +
                      (((ks2 * 2 + mhalf) * 4 + mt) * 128 + lane * 4 + slot);
        g_A[u32i * 2 + par] = __float2half_rn(w);
    }
}

// ---------------------------------------------------------------------------
// Main: GEMM-conv, mma m16n8k16 f16/f32. Tap-major K; x tile staged once;
// B via ldmatrix.x4 from swizzled channel-minor tile.
// Grid (2 dblk, 32 row-pairs, 32 imgs). 256 thr = 8 warps (2 M x 4 N).
// ---------------------------------------------------------------------------
__global__ void __launch_bounds__(256, 2)
conv_main(const float* __restrict__ bias, float* __restrict__ out) {
    extern __shared__ char smraw[];
    uint32_t sb0 = smem_u32(smraw);
    uint32_t sb = (sb0 + 1023) & ~1023u;
    char* sm = smraw + (sb - sb0);

    const int tid = threadIdx.x, wid = tid >> 5, lid = tid & 31;
    const int g = lid >> 2, tig = lid & 3;
    const int warp_m = wid & 1, warp_n = wid >> 1;
    const int dblk = blockIdx.x;
    const int y0 = blockIdx.y * 2;
    const int img = blockIdx.z;

    // ---- stage x tile ONCE: [4 yy][66 xx][128 c] fp16, swizzled ----
    {
        const uint32_t* xTu = (const uint32_t*)g_xT + (size_t)img * (64 * 64 * 64);
        for (int i = 0; i < 66; i++) {
            int e = tid + i * 256;             // 16896 u32
            int yy = e / 4224, rem = e - yy * 4224;
            int xx = rem >> 6, cp = rem & 63;
            int gy = y0 - 1 + yy, gx = xx - 1;
            uint32_t v = 0;
            if ((unsigned)gy < Hh && (unsigned)gx < Ww)
                v = xTu[(gy * 64 + gx) * 64 + cp];
            uint32_t byte = (uint32_t)e * 4;
            byte ^= (byte >> 4) & 0x70;        // xx bits -> 16B slot
            *(uint32_t*)(sm + byte) = v;
        }
    }

    auto cpA = [&](int chunk, int buf) {
        const char* gsrc = (const char*)(g_A) + (size_t)(chunk * 2 + dblk) * 16384 + tid * 64;
        uint32_t sdst = sb + A_OFF + buf * 16384 + tid * 64;
        #pragma unroll
        for (int i = 0; i < 4; i++)
            cp16(sdst + i * 16, gsrc + i * 16);
        asm volatile("cp.async.commit_group;" ::: "memory");
    };

    float acc[4][4][4];
    #pragma unroll
    for (int mt = 0; mt < 4; mt++)
        #pragma unroll
        for (int nt = 0; nt < 4; nt++)
            #pragma unroll
            for (int i = 0; i < 4; i++) acc[mt][nt][i] = 0.f;

    // per-lane ldmatrix invariants
    const int lx = lid & 7, kbit = (lid >> 3) & 1, nh = (lid >> 4) & 1;
    const int y_l = warp_n >> 1, xbase = (warp_n & 1) * 32;

    cpA(0, 0);
    asm volatile("cp.async.wait_group 0;" ::: "memory");
    __syncthreads();

    for (int chunk = 0; chunk < NCH; ++chunk) {
        const int buf = chunk & 1;
        if (chunk + 1 < NCH) cpA(chunk + 1, buf ^ 1);

        const int tap = chunk >> 1, chalf = chunk & 1;
        const int kh = tap / 3, kw = tap - kh * 3;
        // LINEAR base; swizzle applied per access (mask invariant under +ks2*32/+4096)
        const uint32_t byte0 = (uint32_t)(((y_l + kh) * 66 + xbase + nh * 8 + lx + kw) * 256
                                          + kbit * 16 + chalf * 128);
        const uint32_t msk = (byte0 >> 4) & 0x70;
        const uint4* sA = (const uint4*)(sm + A_OFF + buf * 16384);

        #pragma unroll
        for (int ks2 = 0; ks2 < 4; ks2++) {
            uint4 af[4];
            #pragma unroll
            for (int mt = 0; mt < 4; mt++)
                af[mt] = sA[((ks2 * 2 + warp_m) * 4 + mt) * 32 + lid];
            uint32_t a0 = sb + ((byte0 + ks2 * 32) ^ msk);
            uint32_t a1 = sb + ((byte0 + ks2 * 32 + 4096) ^ msk);
            uint32_t r0, r1, r2, r3, s0, s1, s2, s3;
            asm volatile("ldmatrix.sync.aligned.m8n8.x4.shared.b16 {%0,%1,%2,%3}, [%4];"
                         : "=r"(r0), "=r"(r1), "=r"(r2), "=r"(r3)
                         : "r"(a0));
            asm volatile("ldmatrix.sync.aligned.m8n8.x4.shared.b16 {%0,%1,%2,%3}, [%4];"
                         : "=r"(s0), "=r"(s1), "=r"(s2), "=r"(s3)
                         : "r"(a1));
            uint32_t bf[4][2] = {{r0, r1}, {r2, r3}, {s0, s1}, {s2, s3}};
            #pragma unroll
            for (int mt = 0; mt < 4; mt++)
                #pragma unroll
                for (int nt = 0; nt < 4; nt++)
                    asm volatile(
                        "mma.sync.aligned.m16n8k16.row.col.f32.f16.f16.f32 "
                        "{%0,%1,%2,%3}, {%4,%5,%6,%7}, {%8,%9}, {%0,%1,%2,%3};"
                        : "+f"(acc[mt][nt][0]), "+f"(acc[mt][nt][1]),
                          "+f"(acc[mt][nt][2]), "+f"(acc[mt][nt][3])
                        : "r"(af[mt].x), "r"(af[mt].y), "r"(af[mt].z), "r"(af[mt].w),
                          "r"(bf[nt][0]), "r"(bf[nt][1]));
        }

        if (chunk + 1 < NCH)
            asm volatile("cp.async.wait_group 0;" ::: "memory");
        __syncthreads();
    }

    // ---- epilogue (unchanged) ----
    const float b = __ldg(bias);
    #pragma unroll
    for (int mt = 0; mt < 4; mt++) {
        int d = dblk * 128 + warp_m * 64 + mt * 16 + g;
        #pragma unroll
        for (int nt = 0; nt < 4; nt++) {
            int px = warp_n * 32 + nt * 8 + tig * 2;
            int oy = y0 + (px >> 6);
            int ox = px & 63;
            float* o0 = out + (((size_t)img * Dd + d) * Hh + oy) * Ww + ox;
            float* o1 = out + (((size_t)img * Dd + d + 8) * Hh + oy) * Ww + ox;
            *(float2*)o0 = make_float2(acc[mt][nt][0] + b, acc[mt][nt][1] + b);
            *(float2*)o1 = make_float2(acc[mt][nt][2] + b, acc[mt][nt][3] + b);
        }
    }
}

// ---------------------------------------------------------------------------
extern "C" void kernel_launch(void* const* d_in, const int* in_sizes, int n_in,
                              void* d_out, int out_size) {
    const float* x     = (const float*)d_in[0];
    const float* core0 = (const float*)d_in[1];
    const float* core1 = (const float*)d_in[2];
    const float* core2 = (const float*)d_in[3];
    const float* bias  = (const float*)d_in[4];
    float* out = (float*)d_out;

    cudaFuncSetAttribute(conv_main, cudaFuncAttributeMaxDynamicSharedMemorySize, SMEM_MAIN);

    transp_kernel<<<dim3(64, 32), 256>>>(x);
    build_A_kernel<<<Dd, Cc>>>(core0, core1, core2);

    dim3 grid(2, 32, 32);   // dblk, row-pairs, imgs
    conv_main<<<grid, 256, SMEM_MAIN>>>(bias, out);
}

// round 14
// speedup vs baseline: 1.9736x; 1.9736x over previous
#include <cuda_runtime.h>
#include <cuda_fp16.h>
#include <cstdint>

#define Hh 64
#define Ww 64
#define Cc 128
#define Dd 256
#define NCH 18                  // K chunks of 64, k = tap*128 + c (tap-major)
#define SMEM_MAIN (67584 + 1024)

__device__ __half g_xT[(size_t)32 * 64 * 64 * 128];   // [img][y][x][c]
// Pre-permuted fp16 weights: u32 [chunk][dblk][ks2(4)][warp_m(2)][mt(4)][lane(32)][slot(4)]
__device__ __half g_A[NCH * 2 * 8192];

static __device__ __forceinline__ uint32_t smem_u32(const void* p) {
    uint32_t a;
    asm("{ .reg .u64 t; cvta.to.shared.u64 t, %1; cvt.u32.u64 %0, t; }" : "=r"(a) : "l"(p));
    return a;
}

// ---------------------------------------------------------------------------
// Transpose x [img][c][y][x] f32 -> g_xT [img][y][x][c] fp16. Grid (64 y, 32 img).
// ---------------------------------------------------------------------------
__global__ void transp_kernel(const float* __restrict__ x) {
    __shared__ __half sm[64 * 132];
    const int tid = threadIdx.x;
    const int y = blockIdx.x, img = blockIdx.y;
    const float2* src = (const float2*)x;
    #pragma unroll
    for (int i = 0; i < 16; i++) {
        int e = tid + i * 256;             // 4096 float2
        int c = e >> 5, xp = e & 31;
        float2 v = src[(((size_t)img * 128 + c) * 4096 + y * 64) / 2 + xp];
        sm[(2 * xp) * 132 + c]     = __float2half_rn(v.x);
        sm[(2 * xp + 1) * 132 + c] = __float2half_rn(v.y);
    }
    __syncthreads();
    uint32_t* dst = (uint32_t*)g_xT + ((size_t)(img * 64 + y) * 64) * 64;
    #pragma unroll
    for (int i = 0; i < 16; i++) {
        int e = tid + i * 256;             // 4096 u32
        int xx = e >> 6, cp = e & 63;
        dst[xx * 64 + cp] = *(const uint32_t*)&sm[xx * 132 + 2 * cp];
    }
}

// ---------------------------------------------------------------------------
// Build A in m16n8k16 fragment order, K tap-major: k = tap*128 + c.
// ---------------------------------------------------------------------------
__global__ void build_A_kernel(const float* __restrict__ c0,
                               const float* __restrict__ c1,
                               const float* __restrict__ c2) {
    int d = blockIdx.x, t = threadIdx.x;
    __shared__ float sA[72];
    if (t < 72) {
        int r = t / 9, k = t % 9, kh = k / 3, kw = k % 3;
        float a = 0.f;
        #pragma unroll
        for (int s = 0; s < 4; s++)
            a += c1[d * 96 + r * 12 + kh * 4 + s] * c2[d * 12 + s * 3 + kw];
        sA[t] = a;
    }
    __syncthreads();
    int c = t;
    float cr[8];
    #pragma unroll
    for (int r = 0; r < 8; r++) cr[r] = c0[d * 1024 + c * 8 + r];

    const int dblk = d >> 7, ml = d & 127;
    const int mhalf = ml >> 6, mt = (ml >> 4) & 3, mm = ml & 15;
    const int g = mm & 7, hi = mm >> 3;

    #pragma unroll
    for (int tap = 0; tap < 9; tap++) {
        float w = 0.f;
        #pragma unroll
        for (int r = 0; r < 8; r++) w += cr[r] * sA[r * 9 + tap];
        int chunk = tap * 2 + (c >> 6);
        int kr = c & 63;
        int ks2 = kr >> 4, kk = kr & 15;
        int tig = (kk >> 1) & 3, par = kk & 1, khi = kk >> 3;
        int lane = g * 4 + tig, slot = khi * 2 + hi;
        size_t u32i = (size_t)(chunk * 2 + dblk) * 4096 +
                      (((ks2 * 2 + mhalf) * 4 + mt) * 128 + lane * 4 + slot);
        g_A[u32i * 2 + par] = __float2half_rn(w);
    }
}

// ---------------------------------------------------------------------------
// Main: GEMM-conv, mma m16n8k16 f16/f32. Tap-major K; x tile staged once;
// B via ldmatrix.x4; A direct from L2-resident g_A. NO barriers in main loop.
// Grid (2 dblk, 32 row-pairs, 32 imgs). 256 thr = 8 warps (2 M x 4 N).
// ---------------------------------------------------------------------------
__global__ void __launch_bounds__(256, 2)
conv_main(const float* __restrict__ bias, float* __restrict__ out) {
    extern __shared__ char smraw[];
    uint32_t sb0 = smem_u32(smraw);
    uint32_t sb = (sb0 + 1023) & ~1023u;
    char* sm = smraw + (sb - sb0);

    const int tid = threadIdx.x, wid = tid >> 5, lid = tid & 31;
    const int g = lid >> 2, tig = lid & 3;
    const int warp_m = wid & 1, warp_n = wid >> 1;
    const int dblk = blockIdx.x;
    const int y0 = blockIdx.y * 2;
    const int img = blockIdx.z;

    // ---- stage x tile ONCE: [4 yy][66 xx][128 c] fp16, swizzled ----
    {
        const uint32_t* xTu = (const uint32_t*)g_xT + (size_t)img * (64 * 64 * 64);
        for (int i = 0; i < 66; i++) {
            int e = tid + i * 256;             // 16896 u32
            int yy = e / 4224, rem = e - yy * 4224;
            int xx = rem >> 6, cp = rem & 63;
            int gy = y0 - 1 + yy, gx = xx - 1;
            uint32_t v = 0;
            if ((unsigned)gy < Hh && (unsigned)gx < Ww)
                v = xTu[(gy * 64 + gx) * 64 + cp];
            uint32_t byte = (uint32_t)e * 4;
            byte ^= (byte >> 4) & 0x70;        // xx bits -> 16B slot
            *(uint32_t*)(sm + byte) = v;
        }
    }
    __syncthreads();                           // tile ready; no more barriers

    float acc[4][4][4];
    #pragma unroll
    for (int mt = 0; mt < 4; mt++)
        #pragma unroll
        for (int nt = 0; nt < 4; nt++)
            #pragma unroll
            for (int i = 0; i < 4; i++) acc[mt][nt][i] = 0.f;

    // per-lane ldmatrix invariants
    const int lx = lid & 7, kbit = (lid >> 3) & 1, nh = (lid >> 4) & 1;
    const int y_l = warp_n >> 1, xbase = (warp_n & 1) * 32;

    // A base for this warp's dblk/warp_m (uint4 granularity)
    const uint4* __restrict__ Abase =
        (const uint4*)g_A + (size_t)dblk * 1024 + warp_m * 128 + lid;

    for (int chunk = 0; chunk < NCH; ++chunk) {
        const int tap = chunk >> 1, chalf = chunk & 1;
        const int kh = tap / 3, kw = tap - kh * 3;
        // LINEAR base; swizzle applied per access (mask invariant under +ks2*32/+4096)
        const uint32_t byte0 = (uint32_t)(((y_l + kh) * 66 + xbase + nh * 8 + lx + kw) * 256
                                          + kbit * 16 + chalf * 128);
        const uint32_t msk = (byte0 >> 4) & 0x70;
        const uint4* __restrict__ Ac = Abase + (size_t)chunk * 2048;

        #pragma unroll
        for (int ks2 = 0; ks2 < 4; ks2++) {
            uint4 af[4];
            #pragma unroll
            for (int mt = 0; mt < 4; mt++)
                af[mt] = __ldg(&Ac[ks2 * 256 + mt * 32]);
            uint32_t a0 = sb + ((byte0 + ks2 * 32) ^ msk);
            uint32_t a1 = sb + ((byte0 + ks2 * 32 + 4096) ^ msk);
            uint32_t r0, r1, r2, r3, s0, s1, s2, s3;
            asm volatile("ldmatrix.sync.aligned.m8n8.x4.shared.b16 {%0,%1,%2,%3}, [%4];"
                         : "=r"(r0), "=r"(r1), "=r"(r2), "=r"(r3)
                         : "r"(a0));
            asm volatile("ldmatrix.sync.aligned.m8n8.x4.shared.b16 {%0,%1,%2,%3}, [%4];"
                         : "=r"(s0), "=r"(s1), "=r"(s2), "=r"(s3)
                         : "r"(a1));
            uint32_t bf[4][2] = {{r0, r1}, {r2, r3}, {s0, s1}, {s2, s3}};
            #pragma unroll
            for (int mt = 0; mt < 4; mt++)
                #pragma unroll
                for (int nt = 0; nt < 4; nt++)
                    asm volatile(
                        "mma.sync.aligned.m16n8k16.row.col.f32.f16.f16.f32 "
                        "{%0,%1,%2,%3}, {%4,%5,%6,%7}, {%8,%9}, {%0,%1,%2,%3};"
                        : "+f"(acc[mt][nt][0]), "+f"(acc[mt][nt][1]),
                          "+f"(acc[mt][nt][2]), "+f"(acc[mt][nt][3])
                        : "r"(af[mt].x), "r"(af[mt].y), "r"(af[mt].z), "r"(af[mt].w),
                          "r"(bf[nt][0]), "r"(bf[nt][1]));
        }
    }

    // ---- epilogue (unchanged) ----
    const float b = __ldg(bias);
    #pragma unroll
    for (int mt = 0; mt < 4; mt++) {
        int d = dblk * 128 + warp_m * 64 + mt * 16 + g;
        #pragma unroll
        for (int nt = 0; nt < 4; nt++) {
            int px = warp_n * 32 + nt * 8 + tig * 2;
            int oy = y0 + (px >> 6);
            int ox = px & 63;
            float* o0 = out + (((size_t)img * Dd + d) * Hh + oy) * Ww + ox;
            float* o1 = out + (((size_t)img * Dd + d + 8) * Hh + oy) * Ww + ox;
            *(float2*)o0 = make_float2(acc[mt][nt][0] + b, acc[mt][nt][1] + b);
            *(float2*)o1 = make_float2(acc[mt][nt][2] + b, acc[mt][nt][3] + b);
        }
    }
}

// ---------------------------------------------------------------------------
extern "C" void kernel_launch(void* const* d_in, const int* in_sizes, int n_in,
                              void* d_out, int out_size) {
    const float* x     = (const float*)d_in[0];
    const float* core0 = (const float*)d_in[1];
    const float* core1 = (const float*)d_in[2];
    const float* core2 = (const float*)d_in[3];
    const float* bias  = (const float*)d_in[4];
    float* out = (float*)d_out;

    cudaFuncSetAttribute(conv_main, cudaFuncAttributeMaxDynamicSharedMemorySize, SMEM_MAIN);

    transp_kernel<<<dim3(64, 32), 256>>>(x);
    build_A_kernel<<<Dd, Cc>>>(core0, core1, core2);

    dim3 grid(2, 32, 32);   // dblk, row-pairs, imgs
    conv_main<<<grid, 256, SMEM_MAIN>>>(bias, out);
}

// round 15
// speedup vs baseline: 2.2832x; 1.1569x over previous
#include <cuda_runtime.h>
#include <cuda_fp16.h>
#include <cstdint>

#define Hh 64
#define Ww 64
#define Cc 128
#define Dd 256
#define NCH 18                  // K chunks of 64, k = tap*128 + c (tap-major)
#define SMEM_MAIN (67584 + 1024)

__device__ __half g_xT[(size_t)32 * 64 * 64 * 128];   // [img][y][x][c]
// Pre-permuted fp16 weights: u32 [chunk][dblk][ks2(4)][warp_m(2)][mt(4)][lane(32)][slot(4)]
__device__ __half g_A[NCH * 2 * 8192];

static __device__ __forceinline__ uint32_t smem_u32(const void* p) {
    uint32_t a;
    asm("{ .reg .u64 t; cvta.to.shared.u64 t, %1; cvt.u32.u64 %0, t; }" : "=r"(a) : "l"(p));
    return a;
}

// ---------------------------------------------------------------------------
// Transpose x [img][c][y][x] f32 -> g_xT [img][y][x][c] fp16. Grid (64 y, 32 img).
// ---------------------------------------------------------------------------
__global__ void transp_kernel(const float* __restrict__ x) {
    __shared__ __half sm[64 * 132];
    const int tid = threadIdx.x;
    const int y = blockIdx.x, img = blockIdx.y;
    const float2* src = (const float2*)x;
    #pragma unroll
    for (int i = 0; i < 16; i++) {
        int e = tid + i * 256;             // 4096 float2
        int c = e >> 5, xp = e & 31;
        float2 v = src[(((size_t)img * 128 + c) * 4096 + y * 64) / 2 + xp];
        sm[(2 * xp) * 132 + c]     = __float2half_rn(v.x);
        sm[(2 * xp + 1) * 132 + c] = __float2half_rn(v.y);
    }
    __syncthreads();
    uint32_t* dst = (uint32_t*)g_xT + ((size_t)(img * 64 + y) * 64) * 64;
    #pragma unroll
    for (int i = 0; i < 16; i++) {
        int e = tid + i * 256;             // 4096 u32
        int xx = e >> 6, cp = e & 63;
        dst[xx * 64 + cp] = *(const uint32_t*)&sm[xx * 132 + 2 * cp];
    }
}

// ---------------------------------------------------------------------------
// Build A in m16n8k16 fragment order, K tap-major: k = tap*128 + c.
// ---------------------------------------------------------------------------
__global__ void build_A_kernel(const float* __restrict__ c0,
                               const float* __restrict__ c1,
                               const float* __restrict__ c2) {
    int d = blockIdx.x, t = threadIdx.x;
    __shared__ float sA[72];
    if (t < 72) {
        int r = t / 9, k = t % 9, kh = k / 3, kw = k % 3;
        float a = 0.f;
        #pragma unroll
        for (int s = 0; s < 4; s++)
            a += c1[d * 96 + r * 12 + kh * 4 + s] * c2[d * 12 + s * 3 + kw];
        sA[t] = a;
    }
    __syncthreads();
    int c = t;
    float cr[8];
    #pragma unroll
    for (int r = 0; r < 8; r++) cr[r] = c0[d * 1024 + c * 8 + r];

    const int dblk = d >> 7, ml = d & 127;
    const int mhalf = ml >> 6, mt = (ml >> 4) & 3, mm = ml & 15;
    const int g = mm & 7, hi = mm >> 3;

    #pragma unroll
    for (int tap = 0; tap < 9; tap++) {
        float w = 0.f;
        #pragma unroll
        for (int r = 0; r < 8; r++) w += cr[r] * sA[r * 9 + tap];
        int chunk = tap * 2 + (c >> 6);
        int kr = c & 63;
        int ks2 = kr >> 4, kk = kr & 15;
        int tig = (kk >> 1) & 3, par = kk & 1, khi = kk >> 3;
        int lane = g * 4 + tig, slot = khi * 2 + hi;
        size_t u32i = (size_t)(chunk * 2 + dblk) * 4096 +
                      (((ks2 * 2 + mhalf) * 4 + mt) * 128 + lane * 4 + slot);
        g_A[u32i * 2 + par] = __float2half_rn(w);
    }
}

// ---------------------------------------------------------------------------
// Main: GEMM-conv, mma m16n8k16 f16/f32. Tap-major K; x tile staged once;
// B via ldmatrix.x4; A direct from L2-resident g_A. NO barriers in main loop.
// Grid (32 row-pairs, 32 imgs). 512 thr = 16 warps (4 M x 4 N); full 256 d per CTA.
// ---------------------------------------------------------------------------
__global__ void __launch_bounds__(512, 1)
conv_main(const float* __restrict__ bias, float* __restrict__ out) {
    extern __shared__ char smraw[];
    uint32_t sb0 = smem_u32(smraw);
    uint32_t sb = (sb0 + 1023) & ~1023u;
    char* sm = smraw + (sb - sb0);

    const int tid = threadIdx.x, wid = tid >> 5, lid = tid & 31;
    const int g = lid >> 2, tig = lid & 3;
    const int wquad = wid & 3;              // 4-way M: d-quarter
    const int dblk = wquad >> 1, warp_m = wquad & 1;
    const int warp_n = wid >> 2;            // 4-way N
    const int y0 = blockIdx.x * 2;
    const int img = blockIdx.y;

    // ---- stage x tile ONCE: [4 yy][66 xx][128 c] fp16, swizzled ----
    {
        const uint32_t* xTu = (const uint32_t*)g_xT + (size_t)img * (64 * 64 * 64);
        #pragma unroll
        for (int i = 0; i < 33; i++) {
            int e = tid + i * 512;             // 16896 u32
            int yy = e / 4224, rem = e - yy * 4224;
            int xx = rem >> 6, cp = rem & 63;
            int gy = y0 - 1 + yy, gx = xx - 1;
            uint32_t v = 0;
            if ((unsigned)gy < Hh && (unsigned)gx < Ww)
                v = xTu[(gy * 64 + gx) * 64 + cp];
            uint32_t byte = (uint32_t)e * 4;
            byte ^= (byte >> 4) & 0x70;        // xx bits -> 16B slot
            *(uint32_t*)(sm + byte) = v;
        }
    }
    __syncthreads();                           // tile ready; no more barriers

    float acc[4][4][4];
    #pragma unroll
    for (int mt = 0; mt < 4; mt++)
        #pragma unroll
        for (int nt = 0; nt < 4; nt++)
            #pragma unroll
            for (int i = 0; i < 4; i++) acc[mt][nt][i] = 0.f;

    // per-lane ldmatrix invariants
    const int lx = lid & 7, kbit = (lid >> 3) & 1, nh = (lid >> 4) & 1;
    const int y_l = warp_n >> 1, xbase = (warp_n & 1) * 32;

    // A base for this warp's dblk/warp_m (uint4 granularity)
    const uint4* __restrict__ Abase =
        (const uint4*)g_A + (size_t)dblk * 1024 + warp_m * 128 + lid;

    for (int chunk = 0; chunk < NCH; ++chunk) {
        const int tap = chunk >> 1, chalf = chunk & 1;
        const int kh = tap / 3, kw = tap - kh * 3;
        // LINEAR base; swizzle applied per access (mask invariant under +ks2*32/+4096)
        const uint32_t byte0 = (uint32_t)(((y_l + kh) * 66 + xbase + nh * 8 + lx + kw) * 256
                                          + kbit * 16 + chalf * 128);
        const uint32_t msk = (byte0 >> 4) & 0x70;
        const uint4* __restrict__ Ac = Abase + (size_t)chunk * 2048;

        #pragma unroll
        for (int ks2 = 0; ks2 < 4; ks2++) {
            uint4 af[4];
            #pragma unroll
            for (int mt = 0; mt < 4; mt++)
                af[mt] = __ldg(&Ac[ks2 * 256 + mt * 32]);
            uint32_t a0 = sb + ((byte0 + ks2 * 32) ^ msk);
            uint32_t a1 = sb + ((byte0 + ks2 * 32 + 4096) ^ msk);
            uint32_t r0, r1, r2, r3, s0, s1, s2, s3;
            asm volatile("ldmatrix.sync.aligned.m8n8.x4.shared.b16 {%0,%1,%2,%3}, [%4];"
                         : "=r"(r0), "=r"(r1), "=r"(r2), "=r"(r3)
                         : "r"(a0));
            asm volatile("ldmatrix.sync.aligned.m8n8.x4.shared.b16 {%0,%1,%2,%3}, [%4];"
                         : "=r"(s0), "=r"(s1), "=r"(s2), "=r"(s3)
                         : "r"(a1));
            uint32_t bf[4][2] = {{r0, r1}, {r2, r3}, {s0, s1}, {s2, s3}};
            #pragma unroll
            for (int mt = 0; mt < 4; mt++)
                #pragma unroll
                for (int nt = 0; nt < 4; nt++)
                    asm volatile(
                        "mma.sync.aligned.m16n8k16.row.col.f32.f16.f16.f32 "
                        "{%0,%1,%2,%3}, {%4,%5,%6,%7}, {%8,%9}, {%0,%1,%2,%3};"
                        : "+f"(acc[mt][nt][0]), "+f"(acc[mt][nt][1]),
                          "+f"(acc[mt][nt][2]), "+f"(acc[mt][nt][3])
                        : "r"(af[mt].x), "r"(af[mt].y), "r"(af[mt].z), "r"(af[mt].w),
                          "r"(bf[nt][0]), "r"(bf[nt][1]));
        }
    }

    // ---- epilogue (same per-warp pattern; d covers full 256 via wquad) ----
    const float b = __ldg(bias);
    #pragma unroll
    for (int mt = 0; mt < 4; mt++) {
        int d = dblk * 128 + warp_m * 64 + mt * 16 + g;
        #pragma unroll
        for (int nt = 0; nt < 4; nt++) {
            int px = warp_n * 32 + nt * 8 + tig * 2;
            int oy = y0 + (px >> 6);
            int ox = px & 63;
            float* o0 = out + (((size_t)img * Dd + d) * Hh + oy) * Ww + ox;
            float* o1 = out + (((size_t)img * Dd + d + 8) * Hh + oy) * Ww + ox;
            *(float2*)o0 = make_float2(acc[mt][nt][0] + b, acc[mt][nt][1] + b);
            *(float2*)o1 = make_float2(acc[mt][nt][2] + b, acc[mt][nt][3] + b);
        }
    }
}

// ---------------------------------------------------------------------------
extern "C" void kernel_launch(void* const* d_in, const int* in_sizes, int n_in,
                              void* d_out, int out_size) {
    const float* x     = (const float*)d_in[0];
    const float* core0 = (const float*)d_in[1];
    const float* core1 = (const float*)d_in[2];
    const float* core2 = (const float*)d_in[3];
    const float* bias  = (const float*)d_in[4];
    float* out = (float*)d_out;

    cudaFuncSetAttribute(conv_main, cudaFuncAttributeMaxDynamicSharedMemorySize, SMEM_MAIN);

    transp_kernel<<<dim3(64, 32), 256>>>(x);
    build_A_kernel<<<Dd, Cc>>>(core0, core1, core2);

    dim3 grid(32, 32);   // row-pairs, imgs
    conv_main<<<grid, 512, SMEM_MAIN>>>(bias, out);
}